// round 2
// baseline (speedup 1.0000x reference)
#include <cuda_runtime.h>
#include <cuda_bf16.h>

// Problem shape (fixed by the dataset): x1 [B,N1,1], x2 [B,N2,1], scale [1]
// out [B, N1, N2] fp32 = exp(-(x1-x2)^2 / (2*scale^2))
#define B_DIM   4
#define N1_DIM  8192
#define N2_DIM  8192
#define ROWS    4          // output rows per CTA (amortizes x2 reads 4x)

// Each CTA owns ROWS consecutive output rows of one batch.
// 256 threads; each thread covers 8 float4 of the N2 dimension per row.
// Per element: 2 FFMA + 1 MUFU.EX2 via
//   exp(-(a-x)^2 * K) = exp2( C*x^2 + Bc*x + A )
//   Kl = log2(e)/(2 s^2),  C = -Kl,  Bc = 2 a Kl,  A = -a^2 Kl
__global__ __launch_bounds__(256) void rbf_rows_kernel(
    const float* __restrict__ x1,
    const float* __restrict__ x2,
    const float* __restrict__ scale,
    float* __restrict__ out)
{
    const int row0 = blockIdx.x * ROWS;    // first row: b * N1 + n1
    const int b    = row0 >> 13;           // N1_DIM == 8192 == 2^13 (ROWS divides N1)

    const float s  = scale[0];
    const float Kl = 1.44269504088896340736f / (2.0f * s * s);
    const float C  = -Kl;

    float Bc[ROWS], A[ROWS];
#pragma unroll
    for (int r = 0; r < ROWS; r++) {
        const float a = x1[row0 + r];
        Bc[r] = 2.0f * a * Kl;
        A[r]  = -a * a * Kl;
    }

    const float4* __restrict__ x2v  =
        reinterpret_cast<const float4*>(x2) + (size_t)b * (N2_DIM / 4);
    float4* __restrict__ outv =
        reinterpret_cast<float4*>(out) + (size_t)row0 * (N2_DIM / 4);

    const int t = threadIdx.x;

    // Two chunks of 4 front-batched float4 loads (MLP=4), each consumed by
    // ROWS rows of compute + streaming stores.
#pragma unroll
    for (int c = 0; c < 2; c++) {
        float4 v[4];
#pragma unroll
        for (int j = 0; j < 4; j++) {
            v[j] = x2v[t + (c * 4 + j) * 256];   // L1/L2-resident
        }

#pragma unroll
        for (int j = 0; j < 4; j++) {
            const int col = t + (c * 4 + j) * 256;
#pragma unroll
            for (int r = 0; r < ROWS; r++) {
                float4 o;
                o.x = exp2f(fmaf(fmaf(C, v[j].x, Bc[r]), v[j].x, A[r]));
                o.y = exp2f(fmaf(fmaf(C, v[j].y, Bc[r]), v[j].y, A[r]));
                o.z = exp2f(fmaf(fmaf(C, v[j].z, Bc[r]), v[j].z, A[r]));
                o.w = exp2f(fmaf(fmaf(C, v[j].w, Bc[r]), v[j].w, A[r]));
                // Streaming store: written once, never re-read; evict-first
                // keeps x2 hot in L2.
                __stcs(&outv[(size_t)r * (N2_DIM / 4) + col], o);
            }
        }
    }
}

extern "C" void kernel_launch(void* const* d_in, const int* in_sizes, int n_in,
                              void* d_out, int out_size)
{
    const float* x1    = (const float*)d_in[0];
    const float* x2    = (const float*)d_in[1];
    const float* scale = (const float*)d_in[2];
    float*       out   = (float*)d_out;

    (void)in_sizes; (void)n_in; (void)out_size;

    rbf_rows_kernel<<<(B_DIM * N1_DIM) / ROWS, 256>>>(x1, x2, scale, out);
}